// round 14
// baseline (speedup 1.0000x reference)
#include <cuda_runtime.h>
#include <cuda_fp16.h>
#include <stdint.h>

// ---------------------------------------------------------------------------
// RGCN layer, fp16 mma.sync, ATOMIC-FREE edge aggregation:
//   Y[e]  = x[src_e] @ W_rel[etype_e]      (rel-sorted tiles, fp16 stores)
//   S[d]  = sum_{e: dst_e = d} Y[e]        (dst-CSR gather-reduce -> msgh)
//   mid = tanh( x @ (W1x + loop_w@W1m) + S @ W1m + (b1 + rel_bias@W1m) )
//   out = [x, mid] @ W2 + b2
//
//   * operands converted once to fp16; fp32 accumulate in mma
//   * weights pre-transposed to [OUT, K]  (mma .row.col B layout)
//   * edges counting-sorted by relation (GEMM tiles) AND by dst (gather CSR)
//   * 4-stage cp.async pipeline, prefetch distance 2 (K=32 stages, SW64)
//   * CTA tile 128x128, warp tile 64x32, 2 CTAs/SM
// ---------------------------------------------------------------------------

#define N_MAX   100000
#define E_MAX   640000
#define R_MAX   8
#define PERM_PAD (R_MAX * 128)

__device__ __half  g_xh   [(size_t)N_MAX * 128];
__device__ __half  g_msgh [(size_t)N_MAX * 128];
__device__ __half  g_midh [(size_t)N_MAX * 256];
__device__ __half  g_y    [(size_t)(E_MAX + PERM_PAD) * 128];   // per-edge msgs
__device__ __half  g_wrelT[R_MAX * 128 * 128];
__device__ __half  g_w1T  [256 * 256];
__device__ __half  g_w2T  [128 * 384];
__device__ float   g_b1eff[256];
__device__ int g_perm[E_MAX + PERM_PAD];
__device__ int g_epos[E_MAX];          // edge -> padded perm position
__device__ int g_dcnt[N_MAX];          // per-dst degree
__device__ int g_doff[N_MAX];          // exclusive scan of dcnt
__device__ int g_dcur[N_MAX];
__device__ int g_dperm[E_MAX];         // dst-sorted list of perm positions
__device__ int g_bsum[128];            // scan block sums
__device__ int g_cnt[R_MAX];
__device__ int g_cur[R_MAX];

// ---- helpers ---------------------------------------------------------------
__device__ __forceinline__ uint32_t smem_u32(const void* p) {
    uint32_t a;
    asm("{ .reg .u64 t; cvta.to.shared.u64 t, %1; cvt.u32.u64 %0, t; }"
        : "=r"(a) : "l"(p));
    return a;
}

#define CPA16(sm, gp) \
    asm volatile("cp.async.cg.shared.global [%0], [%1], 16;" \
                 :: "r"(sm), "l"(gp) : "memory")
#define CPA_COMMIT() \
    asm volatile("cp.async.commit_group;" ::: "memory")
#define CPA_WAIT2() \
    asm volatile("cp.async.wait_group 2;" ::: "memory")
#define CPA_WAIT1() \
    asm volatile("cp.async.wait_group 1;" ::: "memory")
#define CPA_WAIT0() \
    asm volatile("cp.async.wait_group 0;" ::: "memory")

__device__ __forceinline__ void ldsm4(uint32_t* r, uint32_t addr) {
    asm volatile("ldmatrix.sync.aligned.m8n8.x4.shared.b16 {%0,%1,%2,%3}, [%4];"
        : "=r"(r[0]), "=r"(r[1]), "=r"(r[2]), "=r"(r[3]) : "r"(addr));
}
__device__ __forceinline__ void mma16816(float* d, const uint32_t* a,
                                         const uint32_t* b) {
    asm volatile(
        "mma.sync.aligned.m16n8k16.row.col.f32.f16.f16.f32 "
        "{%0,%1,%2,%3}, {%4,%5,%6,%7}, {%8,%9}, {%0,%1,%2,%3};"
        : "+f"(d[0]), "+f"(d[1]), "+f"(d[2]), "+f"(d[3])
        : "r"(a[0]), "r"(a[1]), "r"(a[2]), "r"(a[3]), "r"(b[0]), "r"(b[1]));
}
__device__ __forceinline__ float tanh_fast(float x) {
    float e;
    asm("ex2.approx.f32 %0, %1;" : "=f"(e) : "f"(x * 2.8853900817779268f));
    return 1.0f - __fdividef(2.0f, e + 1.0f);
}
__device__ __forceinline__ uint32_t pack2h(float a, float b) {
    return (uint32_t)__half_as_ushort(__float2half_rn(a)) |
           ((uint32_t)__half_as_ushort(__float2half_rn(b)) << 16);
}

// ---- fp32 -> fp16 convert; also zeroes counters ----------------------------
__global__ void k_cvtx(const float* __restrict__ in,
                       __half* __restrict__ out16, int n4, int N) {
    int i = blockIdx.x * blockDim.x + threadIdx.x;
    if (blockIdx.x == 0 && threadIdx.x < R_MAX) {
        g_cnt[threadIdx.x] = 0;
        g_cur[threadIdx.x] = 0;
    }
    if (i < N) g_dcnt[i] = 0;
    if (i >= n4) return;
    float4 v = ((const float4*)in)[i];
    uint2 p;
    p.x = pack2h(v.x, v.y);
    p.y = pack2h(v.z, v.w);
    ((uint2*)out16)[i] = p;
}

// ---- merged prep: perm init + rel hist + dst hist + W_rel transpose --------
__global__ void k_prep(const int* __restrict__ etype,
                       const int* __restrict__ dst, int E, int P,
                       const float* __restrict__ wrel) {
    __shared__ int h[R_MAX];
    int tid = threadIdx.x;
    if (tid < R_MAX) h[tid] = 0;
    __syncthreads();
    int i = blockIdx.x * blockDim.x + tid;
    if (i < P) g_perm[i] = -1;
    if (i < E) {
        atomicAdd(&h[etype[i]], 1);
        atomicAdd(&g_dcnt[dst[i]], 1);
    }
    if (i < R_MAX * 128 * 128) {
        int r = i >> 14, rem = i & 16383;
        int k = rem >> 7, o = rem & 127;
        g_wrelT[(size_t)r * 16384 + (size_t)o * 128 + k] =
            __float2half_rn(wrel[i]);
    }
    __syncthreads();
    if (tid < R_MAX && h[tid]) atomicAdd(&g_cnt[tid], h[tid]);
}

// ---- counting-sort scatter by relation; records edge -> position -----------
__global__ void k_scatter(const int* __restrict__ etype, int E) {
    __shared__ int h[R_MAX], base[R_MAX], off[R_MAX];
    int tid = threadIdx.x;
    if (tid < R_MAX) {
        h[tid] = 0;
        int o = 0;
        for (int r = 0; r < tid; r++) o += (g_cnt[r] + 127) & ~127;
        off[tid] = o;
    }
    __syncthreads();
    int e = blockIdx.x * blockDim.x + tid;
    int r = -1, rank = 0;
    if (e < E) { r = etype[e]; rank = atomicAdd(&h[r], 1); }
    __syncthreads();
    if (tid < R_MAX && h[tid]) base[tid] = atomicAdd(&g_cur[tid], h[tid]);
    __syncthreads();
    if (e < E) {
        int p = off[r] + base[r] + rank;
        g_perm[p] = e;
        g_epos[e] = p;
    }
}

// ---- exclusive scan of g_dcnt -> g_doff (3 small launches) ----------------
__device__ __forceinline__ int block_scan_incl(int v, int* ws, int tid) {
    int x = v;
#pragma unroll
    for (int o = 1; o < 32; o <<= 1) {
        int t = __shfl_up_sync(0xFFFFFFFFu, x, o);
        if ((tid & 31) >= o) x += t;
    }
    if ((tid & 31) == 31) ws[tid >> 5] = x;
    __syncthreads();
    if (tid < 32) {
        int y = ws[tid];
#pragma unroll
        for (int o = 1; o < 32; o <<= 1) {
            int t = __shfl_up_sync(0xFFFFFFFFu, y, o);
            if (tid >= o) y += t;
        }
        ws[tid] = y;
    }
    __syncthreads();
    return x + ((tid >= 32) ? ws[(tid >> 5) - 1] : 0);
}
__global__ void k_dscan1(int N) {
    __shared__ int ws[32];
    int tid = threadIdx.x;
    int i = blockIdx.x * 1024 + tid;
    int v = (i < N) ? g_dcnt[i] : 0;
    int incl = block_scan_incl(v, ws, tid);
    if (i < N) { g_doff[i] = incl - v; g_dcur[i] = 0; }
    if (tid == 1023) g_bsum[blockIdx.x] = incl;
}
__global__ void k_dscan2(int NB) {
    __shared__ int ws[32];
    int tid = threadIdx.x;
    int v = (tid < NB) ? g_bsum[tid] : 0;
    int incl = block_scan_incl(v, ws, tid);
    if (tid < NB) g_bsum[tid] = incl - v;     // exclusive
}
__global__ void k_dscan3(int N) {
    int i = blockIdx.x * 1024 + threadIdx.x;
    if (i < N) g_doff[i] += g_bsum[blockIdx.x];
}

// ---- dst-sorted permutation of perm positions ------------------------------
__global__ void k_dscatter(const int* __restrict__ dst, int E) {
    int e = blockIdx.x * blockDim.x + threadIdx.x;
    if (e >= E) return;
    int d = dst[e];
    int r = atomicAdd(&g_dcur[d], 1);
    g_dperm[g_doff[d] + r] = g_epos[e];
}

// ---- gather-reduce: one warp per dst row; writes msgh fp16 -----------------
__global__ void k_gather(int N, int E) {
    int w = (blockIdx.x * blockDim.x + threadIdx.x) >> 5;
    int lane = threadIdx.x & 31;
    if (w >= N) return;
    int beg = g_doff[w];
    int end = (w == N - 1) ? E : g_doff[w + 1];
    float a0 = 0.f, a1 = 0.f, a2 = 0.f, a3 = 0.f;
    for (int j = beg; j < end; ++j) {
        int p = g_dperm[j];
        uint2 hv = *(const uint2*)((const unsigned short*)g_y +
                                   (size_t)p * 128 + lane * 4);
        __half2 h0 = *(__half2*)&hv.x, h1 = *(__half2*)&hv.y;
        float2 f0 = __half22float2(h0), f1 = __half22float2(h1);
        a0 += f0.x; a1 += f0.y; a2 += f1.x; a3 += f1.y;
    }
    uint2 o;
    o.x = pack2h(a0, a1);
    o.y = pack2h(a2, a3);
    *(uint2*)((unsigned short*)g_msgh + (size_t)w * 128 + lane * 4) = o;
}

// ---- W2 transpose: [384, 128] -> [128, 384] fp16 ---------------------------
__global__ void k_prepw2(const float* __restrict__ in) {
    int i = blockIdx.x * blockDim.x + threadIdx.x;
    if (i >= 384 * 128) return;
    int k = i >> 7, o = i & 127;
    g_w2T[(size_t)o * 384 + k] = __float2half_rn(in[i]);
}

// ---- fold loop_w / rel_bias into W1 (fp32 exact), then fp16 ----------------
__global__ void k_foldw1(const float* __restrict__ W1,
                         const float* __restrict__ loop_w,
                         const float* __restrict__ rel_bias,
                         const float* __restrict__ b1) {
    int i = blockIdx.x * blockDim.x + threadIdx.x;
    if (i < 256 * 256) {
        int k = i >> 8, o = i & 255;
        float s = W1[(size_t)k * 256 + o];
        if (k < 128) {
            const float* lw = loop_w + (size_t)k * 128;
#pragma unroll 4
            for (int j = 0; j < 128; j++)
                s += lw[j] * W1[(size_t)(128 + j) * 256 + o];
        }
        g_w1T[(size_t)o * 256 + k] = __float2half_rn(s);
    } else if (i < 256 * 256 + 256) {
        int o = i - 256 * 256;
        float s = b1[o];
        for (int j = 0; j < 128; j++)
            s += rel_bias[j] * W1[(size_t)(128 + j) * 256 + o];
        g_b1eff[o] = s;
    }
}

// ---------------------------------------------------------------------------
// Unified fp16 HMMA GEMM. MODE: 1=edge(Y stores), 2=MLP1, 3=MLP2
// 256 threads = 8 warps (2 m x 4 n); CTA tile 128x128; warp tile 64x32.
// K in 32-wide stages; per stage: A 128rx64B + B 128rx64B = 16KB, SW64
// swizzle; FOUR stage buffers, prefetch distance 2, one sync per stage.
// ---------------------------------------------------------------------------
static constexpr int TILE_B  = 8192;                 // 128 rows x 64 B
static constexpr int STAGE_B = 2 * TILE_B;           // 16 KB
static constexpr int NSTAGE  = 4;
static constexpr int SMEM_DYN = 1024 + 2048 + NSTAGE * STAGE_B;

template<int MODE>
__global__ void __launch_bounds__(256, 2)
gemm_rgcn(const int* __restrict__ src, const int* __restrict__ dst,
          const int* __restrict__ etype,
          const float* __restrict__ bias,
          float* __restrict__ outp, int N)
{
    constexpr int CH   = (MODE == 2) ? 8 : (MODE == 3) ? 12 : 4;   // 32-k stages
    constexpr int KTOT = (MODE == 2) ? 256 : (MODE == 3) ? 384 : 128;

    extern __shared__ char dynsmem[];
    uint32_t sb0 = smem_u32(dynsmem);
    uint32_t sb  = (sb0 + 1023) & ~1023u;
    char* smp = dynsmem + (sb - sb0);

    const int tid = threadIdx.x;
    const int coloff = blockIdx.y * 128;
    const int rowbase = blockIdx.x * 128;
    int* s_meta = (int*)smp;
    int* s_src  = (int*)(smp + 16);
    const uint32_t STG0 = sb + 2048;

    int rel = 0;
    if constexpr (MODE == 1) {
        if (tid < 128) {
            int e = g_perm[rowbase + tid];
            s_src[tid] = (e >= 0) ? src[e] : 0;
            if (tid == 0) s_meta[0] = (e >= 0) ? etype[e] : -1;
        }
        __syncthreads();
        rel = s_meta[0];
        if (rel < 0) return;                 // fully-padded tile
    }

    // ---- loader geometry: thread covers rows r0 and r0+64, 16B chunk qid
    const int r0 = tid >> 2, qid = tid & 3;
    int arow0, arow1;
    if constexpr (MODE == 1) { arow0 = s_src[r0]; arow1 = s_src[r0 + 64]; }
    else {
        arow0 = rowbase + r0;      if (arow0 > N - 1) arow0 = N - 1;
        arow1 = rowbase + r0 + 64; if (arow1 > N - 1) arow1 = N - 1;
    }
    // SW64 swizzled smem offsets (chunk ^ ((row&6)<<3)); row+64 keeps (row&6)
    const uint32_t sd0 = (uint32_t)r0 * 64 + (uint32_t)((qid * 16) ^ ((r0 & 6) << 3));
    const uint32_t sd1 = sd0 + 64 * 64;

    // ---- fragment geometry
    const int L  = tid & 31, wid = tid >> 5;
    const int wm = (wid & 1) * 64, wn = (wid >> 1) * 32;
    const int lr15 = L & 15;
    const uint32_t swz = (uint32_t)((lr15 & 6) << 3);
    const uint32_t rowA = (uint32_t)(wm + lr15) * 64;
    const uint32_t rowB = (uint32_t)(wn + lr15) * 64;
    uint32_t cbx[2];
#pragma unroll
    for (int ks = 0; ks < 2; ks++)
        cbx[ks] = (uint32_t)(((L >> 4) * 16 + ks * 32)) ^ swz;

    float acc[4][4][4];
#pragma unroll
    for (int mi = 0; mi < 4; mi++)
#pragma unroll
        for (int ni = 0; ni < 4; ni++)
#pragma unroll
            for (int q = 0; q < 4; q++) acc[mi][ni][q] = 0.0f;

    // ---- stage issue: 4 x 16B cp.async into buffer (c % 4)
    auto issue = [&](int c) {
        const __half *pa, *pb;
        size_t ka, abase;
        if (MODE == 2 && c >= 4)      { pa = g_msgh; ka = 128; abase = (size_t)(c - 4) * 32; }
        else if (MODE == 3 && c >= 4) { pa = g_midh; ka = 256; abase = (size_t)(c - 4) * 32; }
        else                          { pa = g_xh;   ka = 128; abase = (size_t)c * 32; }
        if (MODE == 1)      pb = g_wrelT + (size_t)rel * 16384;
        else if (MODE == 2) pb = g_w1T;
        else                pb = g_w2T;
        const size_t a0 = (size_t)arow0 * ka + abase + (size_t)qid * 8;
        const size_t a1 = (size_t)arow1 * ka + abase + (size_t)qid * 8;
        const size_t b0 = (size_t)(coloff + r0) * KTOT + (size_t)c * 32 + (size_t)qid * 8;
        const size_t b1 = b0 + (size_t)64 * KTOT;
        const uint32_t ST = STG0 + (uint32_t)(c % NSTAGE) * STAGE_B;
        const uint32_t A = ST, B = ST + TILE_B;
        CPA16(A + sd0, (const char*)(pa + a0));
        CPA16(A + sd1, (const char*)(pa + a1));
        CPA16(B + sd0, (const char*)(pb + b0));
        CPA16(B + sd1, (const char*)(pb + b1));
        CPA_COMMIT();
    };

    issue(0);
    issue(1);
    issue(2);

#pragma unroll 1
    for (int c = 0; c < CH; ++c) {
        const int rem = CH - 1 - c;
        if (rem >= 2)      CPA_WAIT2();     // stages <= c complete
        else if (rem == 1) CPA_WAIT1();
        else               CPA_WAIT0();
        __syncthreads();           // stage c ready; all warps done with c-1
        if (c + 3 < CH) issue(c + 3);   // writes (c+3)%4 == (c-1)%4: safe

        const uint32_t ST = STG0 + (uint32_t)(c % NSTAGE) * STAGE_B;
        const uint32_t A = ST, B = ST + TILE_B;

#pragma unroll
        for (int ks = 0; ks < 2; ++ks) {
            const uint32_t ko = cbx[ks];
            uint32_t aF[4][4], bF[4][2];
            {
                uint32_t bq[4], bq2[4];
                ldsm4(bq,  B + rowB + ko);
                ldsm4(bq2, B + rowB + 1024 + ko);
                bF[0][0] = bq[0];  bF[0][1] = bq[2];
                bF[1][0] = bq[1];  bF[1][1] = bq[3];
                bF[2][0] = bq2[0]; bF[2][1] = bq2[2];
                bF[3][0] = bq2[1]; bF[3][1] = bq2[3];
            }
#pragma unroll
            for (int mi = 0; mi < 4; ++mi)
                ldsm4(aF[mi], A + rowA + mi * 1024 + ko);
#pragma unroll
            for (int mi = 0; mi < 4; ++mi)
#pragma unroll
                for (int ni = 0; ni < 4; ++ni)
                    mma16816(acc[mi][ni], aF[mi], bF[ni]);
        }
    }

    // ---- epilogue ----
    const int g = L >> 2, t2 = (L & 3) * 2;
    if constexpr (MODE == 1) {
        // shfl-pack fragment pairs into 4-col quads -> fp16 STG to Y
        const int half = (L & 3) >> 1;           // cols half*4 .. half*4+3
        const int niA  = (L & 1) * 2;            // this lane stores niA, niA+1
#pragma unroll
        for (int mi = 0; mi < 4; ++mi)
#pragma unroll
            for (int h = 0; h < 2; ++h) {
                int yrow = rowbase + wm + mi * 16 + g + h * 8;
                float q[4][4];
#pragma unroll
                for (int ni = 0; ni < 4; ++ni) {
                    float vx = acc[mi][ni][h * 2];
                    float vy = acc[mi][ni][h * 2 + 1];
                    float px = __shfl_xor_sync(0xFFFFFFFFu, vx, 1);
                    float py = __shfl_xor_sync(0xFFFFFFFFu, vy, 1);
                    if ((L & 1) == 0) { q[ni][0] = vx; q[ni][1] = vy; q[ni][2] = px; q[ni][3] = py; }
                    else              { q[ni][0] = px; q[ni][1] = py; q[ni][2] = vx; q[ni][3] = vy; }
                }
                unsigned short* yp = (unsigned short*)g_y +
                                     (size_t)yrow * 128 + wn + half * 4;
#pragma unroll
                for (int u = 0; u < 2; ++u) {
                    int ni = niA + u;
                    uint2 o;
                    o.x = pack2h(q[ni][0], q[ni][1]);
                    o.y = pack2h(q[ni][2], q[ni][3]);
                    *(uint2*)(yp + ni * 8) = o;
                }
            }
    } else if constexpr (MODE == 2) {
        float2 bb[4];
#pragma unroll
        for (int ni = 0; ni < 4; ++ni)
            bb[ni] = *(const float2*)(bias + coloff + wn + ni * 8 + t2);
#pragma unroll
        for (int mi = 0; mi < 4; ++mi)
#pragma unroll
            for (int h = 0; h < 2; ++h) {
                int r = rowbase + wm + mi * 16 + g + h * 8;
                if (r > N - 1) r = N - 1;
                size_t off = (size_t)r * 256 + coloff + wn + t2;
#pragma unroll
                for (int ni = 0; ni < 4; ++ni) {
                    float vx = tanh_fast(acc[mi][ni][h * 2]     + bb[ni].x);
                    float vy = tanh_fast(acc[mi][ni][h * 2 + 1] + bb[ni].y);
                    *(uint32_t*)((unsigned short*)g_midh + off + ni * 8) =
                        pack2h(vx, vy);
                }
            }
    } else {
        float2 bb[4];
#pragma unroll
        for (int ni = 0; ni < 4; ++ni)
            bb[ni] = *(const float2*)(bias + wn + ni * 8 + t2);
#pragma unroll
        for (int mi = 0; mi < 4; ++mi)
#pragma unroll
            for (int h = 0; h < 2; ++h) {
                int r = rowbase + wm + mi * 16 + g + h * 8;
                if (r > N - 1) r = N - 1;
                float* rp = outp + (size_t)r * 128 + wn + t2;
#pragma unroll
                for (int ni = 0; ni < 4; ++ni) {
                    float2 v;
                    v.x = acc[mi][ni][h * 2]     + bb[ni].x;
                    v.y = acc[mi][ni][h * 2 + 1] + bb[ni].y;
                    *(float2*)(rp + ni * 8) = v;
                }
            }
    }
}

// ---------------------------------------------------------------------------
extern "C" void kernel_launch(void* const* d_in, const int* in_sizes, int n_in,
                              void* d_out, int out_size)
{
    const float* x        = (const float*)d_in[0];
    const int*   src      = (const int*)  d_in[1];
    const int*   dst      = (const int*)  d_in[2];
    const int*   etype    = (const int*)  d_in[3];
    const float* W_rel    = (const float*)d_in[4];
    const float* loop_w   = (const float*)d_in[5];
    const float* rel_bias = (const float*)d_in[6];
    const float* W1       = (const float*)d_in[7];
    const float* b1       = (const float*)d_in[8];
    const float* W2       = (const float*)d_in[9];
    const float* b2       = (const float*)d_in[10];
    float* out = (float*)d_out;

    const int N = in_sizes[0] / 128;
    const int E = in_sizes[1];

    float* b1eff;
    __half *xh;
    cudaGetSymbolAddress((void**)&b1eff, g_b1eff);
    cudaGetSymbolAddress((void**)&xh,    g_xh);

    cudaFuncSetAttribute(gemm_rgcn<1>, cudaFuncAttributeMaxDynamicSharedMemorySize, SMEM_DYN);
    cudaFuncSetAttribute(gemm_rgcn<2>, cudaFuncAttributeMaxDynamicSharedMemorySize, SMEM_DYN);
    cudaFuncSetAttribute(gemm_rgcn<3>, cudaFuncAttributeMaxDynamicSharedMemorySize, SMEM_DYN);

    const int P = E + PERM_PAD;
    const int tilesM = (N + 127) / 128;
    const int tilesE = (P + 127) / 128;
    const int NB = (N + 1023) / 1024;            // scan blocks (<= 128)

    // 1. convert x to fp16 (also zeroes g_cnt, g_cur, g_dcnt)
    k_cvtx<<<(N * 32 + 255) / 256, 256>>>(x, xh, N * 32, N);
    // 2. perm init + rel/dst histograms + W_rel transpose (merged)
    k_prep<<<(P + 255) / 256, 256>>>(etype, dst, E, P, W_rel);
    // 3. counting-sort scatter by relation (also records edge positions)
    k_scatter<<<(E + 255) / 256, 256>>>(etype, E);
    // 4. Y[p] = x[src] @ W_rel[etype]  (fp16 stores)  -- PROFILED SLOT
    gemm_rgcn<1><<<tilesE, 256, SMEM_DYN>>>(src, dst, etype, nullptr, nullptr, N);
    // 5-7. exclusive scan of dst degrees -> g_doff
    k_dscan1<<<NB, 1024>>>(N);
    k_dscan2<<<1, 1024>>>(NB);
    k_dscan3<<<NB, 1024>>>(N);
    // 8. dst-sorted permutation
    k_dscatter<<<(E + 255) / 256, 256>>>(dst, E);
    // 9. S[d] = sum Y[incoming] -> msgh (fp16)
    k_gather<<<(N * 32 + 255) / 256, 256>>>(N, E);
    // 10. fold loop_w / rel_bias into W1 -> w1T, b1eff
    k_foldw1<<<(256 * 256 + 256 + 255) / 256, 256>>>(W1, loop_w, rel_bias, b1);
    // 11. W2 transpose
    k_prepw2<<<(384 * 128 + 255) / 256, 256>>>(W2);
    // 12. mid = tanh(x @ w1x' + S @ w1m + b1eff) -> fp16
    gemm_rgcn<2><<<dim3(tilesM, 2), 256, SMEM_DYN>>>(nullptr, nullptr, nullptr,
                                                     b1eff, nullptr, N);
    // 13. out = [x, mid] @ W2 + b2
    gemm_rgcn<3><<<tilesM, 256, SMEM_DYN>>>(nullptr, nullptr, nullptr,
                                            b2, out, N);
}

// round 17
// speedup vs baseline: 1.1585x; 1.1585x over previous
#include <cuda_runtime.h>
#include <cuda_fp16.h>
#include <stdint.h>

// ---------------------------------------------------------------------------
// RGCN layer, fp16 mma.sync (plain sm_103 target):
//   S   = segsum_dst( x[src] @ W_rel[etype] )     (quad REDs into zeroed S)
//   mid = tanh( x @ (W1x + loop_w@W1m) + S @ W1m + (b1 + rel_bias@W1m) )
//   out = [x, mid] @ W2 + b2
//
//   * fp16 single-pass operands, fp32 mma accumulate
//   * edge kernel is PERSISTENT over ~9 relation-sorted tiles per CTA with
//     W_rel resident in smem -> halves cp.async issue traffic (the measured
//     bottleneck: LDGSTS rt=8cyc/SMSP caps cp.async at ~2.1 TB/s chip-wide)
//   * 4-stage cp.async pipeline, prefetch distance 2 (K=32 stages, SW64)
//   * CTA tile 128x128, warp tile 64x32, 2 CTAs/SM
// ---------------------------------------------------------------------------

#define N_MAX   100000
#define E_MAX   640000
#define R_MAX   8
#define PERM_PAD (R_MAX * 128)

__device__ float   g_msg  [(size_t)N_MAX * 128];      // S (edge sums, fp32)
__device__ __half  g_xh   [(size_t)N_MAX * 128];
__device__ __half  g_msgh [(size_t)N_MAX * 128];
__device__ __half  g_midh [(size_t)N_MAX * 256];
__device__ __half  g_wrelT[R_MAX * 128 * 128];
__device__ __half  g_w1T  [256 * 256];
__device__ __half  g_w2T  [128 * 384];
__device__ float   g_b1eff[256];
__device__ int g_perm[E_MAX + PERM_PAD];
__device__ int g_cnt[R_MAX];
__device__ int g_cur[R_MAX];

// ---- helpers ---------------------------------------------------------------
__device__ __forceinline__ uint32_t smem_u32(const void* p) {
    uint32_t a;
    asm("{ .reg .u64 t; cvta.to.shared.u64 t, %1; cvt.u32.u64 %0, t; }"
        : "=r"(a) : "l"(p));
    return a;
}

#define CPA16(sm, gp) \
    asm volatile("cp.async.cg.shared.global [%0], [%1], 16;" \
                 :: "r"(sm), "l"(gp) : "memory")
#define CPA_COMMIT() \
    asm volatile("cp.async.commit_group;" ::: "memory")
#define CPA_WAIT2() \
    asm volatile("cp.async.wait_group 2;" ::: "memory")
#define CPA_WAIT1() \
    asm volatile("cp.async.wait_group 1;" ::: "memory")
#define CPA_WAIT0() \
    asm volatile("cp.async.wait_group 0;" ::: "memory")

__device__ __forceinline__ void ldsm4(uint32_t* r, uint32_t addr) {
    asm volatile("ldmatrix.sync.aligned.m8n8.x4.shared.b16 {%0,%1,%2,%3}, [%4];"
        : "=r"(r[0]), "=r"(r[1]), "=r"(r[2]), "=r"(r[3]) : "r"(addr));
}
__device__ __forceinline__ void mma16816(float* d, const uint32_t* a,
                                         const uint32_t* b) {
    asm volatile(
        "mma.sync.aligned.m16n8k16.row.col.f32.f16.f16.f32 "
        "{%0,%1,%2,%3}, {%4,%5,%6,%7}, {%8,%9}, {%0,%1,%2,%3};"
        : "+f"(d[0]), "+f"(d[1]), "+f"(d[2]), "+f"(d[3])
        : "r"(a[0]), "r"(a[1]), "r"(a[2]), "r"(a[3]), "r"(b[0]), "r"(b[1]));
}
__device__ __forceinline__ float tanh_fast(float x) {
    float e;
    asm("ex2.approx.f32 %0, %1;" : "=f"(e) : "f"(x * 2.8853900817779268f));
    return 1.0f - __fdividef(2.0f, e + 1.0f);
}
__device__ __forceinline__ uint32_t pack2h(float a, float b) {
    return (uint32_t)__half_as_ushort(__float2half_rn(a)) |
           ((uint32_t)__half_as_ushort(__float2half_rn(b)) << 16);
}

// ---- fp32 -> fp16 convert; also zeroes S, g_cnt, g_cur ---------------------
__global__ void k_cvtx(const float* __restrict__ in,
                       __half* __restrict__ out16, int n4) {
    int i = blockIdx.x * blockDim.x + threadIdx.x;
    if (blockIdx.x == 0 && threadIdx.x < R_MAX) {
        g_cnt[threadIdx.x] = 0;
        g_cur[threadIdx.x] = 0;
    }
    if (i >= n4) return;
    ((float4*)g_msg)[i] = make_float4(0.f, 0.f, 0.f, 0.f);   // zero S
    float4 v = ((const float4*)in)[i];
    uint2 p;
    p.x = pack2h(v.x, v.y);
    p.y = pack2h(v.z, v.w);
    ((uint2*)out16)[i] = p;
}

// ---- plain fp32 -> fp16 convert (for S) ------------------------------------
__global__ void k_cvt(const float* __restrict__ in,
                      __half* __restrict__ out16, int n4) {
    int i = blockIdx.x * blockDim.x + threadIdx.x;
    if (i >= n4) return;
    float4 v = ((const float4*)in)[i];
    uint2 p;
    p.x = pack2h(v.x, v.y);
    p.y = pack2h(v.z, v.w);
    ((uint2*)out16)[i] = p;
}

// ---- merged prep: perm init + relation histogram + W_rel transpose ---------
__global__ void k_prep(const int* __restrict__ etype, int E, int P,
                       const float* __restrict__ wrel) {
    __shared__ int h[R_MAX];
    int tid = threadIdx.x;
    if (tid < R_MAX) h[tid] = 0;
    __syncthreads();
    int i = blockIdx.x * blockDim.x + tid;
    if (i < P) g_perm[i] = -1;
    if (i < E) atomicAdd(&h[etype[i]], 1);
    if (i < R_MAX * 128 * 128) {
        int r = i >> 14, rem = i & 16383;
        int k = rem >> 7, o = rem & 127;
        g_wrelT[(size_t)r * 16384 + (size_t)o * 128 + k] =
            __float2half_rn(wrel[i]);
    }
    __syncthreads();
    if (tid < R_MAX && h[tid]) atomicAdd(&g_cnt[tid], h[tid]);
}

// ---- counting-sort scatter (per-block redundant padded prefix) ------------
__global__ void k_scatter(const int* __restrict__ etype, int E) {
    __shared__ int h[R_MAX], base[R_MAX], off[R_MAX];
    int tid = threadIdx.x;
    if (tid < R_MAX) {
        h[tid] = 0;
        int o = 0;
        for (int r = 0; r < tid; r++) o += (g_cnt[r] + 127) & ~127;
        off[tid] = o;
    }
    __syncthreads();
    int e = blockIdx.x * blockDim.x + tid;
    int r = -1, rank = 0;
    if (e < E) { r = etype[e]; rank = atomicAdd(&h[r], 1); }
    __syncthreads();
    if (tid < R_MAX && h[tid]) base[tid] = atomicAdd(&g_cur[tid], h[tid]);
    __syncthreads();
    if (e < E) g_perm[off[r] + base[r] + rank] = e;
}

// ---- W2 transpose: [384, 128] -> [128, 384] fp16 ---------------------------
__global__ void k_prepw2(const float* __restrict__ in) {
    int i = blockIdx.x * blockDim.x + threadIdx.x;
    if (i >= 384 * 128) return;
    int k = i >> 7, o = i & 127;
    g_w2T[(size_t)o * 384 + k] = __float2half_rn(in[i]);
}

// ---- fold loop_w / rel_bias into W1 (fp32 exact), then fp16 ----------------
__global__ void k_foldw1(const float* __restrict__ W1,
                         const float* __restrict__ loop_w,
                         const float* __restrict__ rel_bias,
                         const float* __restrict__ b1) {
    int i = blockIdx.x * blockDim.x + threadIdx.x;
    if (i < 256 * 256) {
        int k = i >> 8, o = i & 255;
        float s = W1[(size_t)k * 256 + o];
        if (k < 128) {
            const float* lw = loop_w + (size_t)k * 128;
#pragma unroll 4
            for (int j = 0; j < 128; j++)
                s += lw[j] * W1[(size_t)(128 + j) * 256 + o];
        }
        g_w1T[(size_t)o * 256 + k] = __float2half_rn(s);
    } else if (i < 256 * 256 + 256) {
        int o = i - 256 * 256;
        float s = b1[o];
        for (int j = 0; j < 128; j++)
            s += rel_bias[j] * W1[(size_t)(128 + j) * 256 + o];
        g_b1eff[o] = s;
    }
}

// ---------------------------------------------------------------------------
// Persistent edge kernel: each CTA processes T consecutive 128-edge tiles
// (relation-sorted), keeping the 32KB W_rel tile RESIDENT in smem and
// reloading it only on relation changes. A (gathered x rows) streams through
// a 4-buffer cp.async ring, prefetch distance 2. Epilogue: quad REDs into S.
// ---------------------------------------------------------------------------
static constexpr int TILE_B  = 8192;                 // 128 rows x 64 B
static constexpr int SMEM_E  = 1024 + 2048 + 32768 /*B*/ + 4 * TILE_B /*A*/;

__global__ void __launch_bounds__(256, 2)
k_edge(const int* __restrict__ src, const int* __restrict__ dst,
       const int* __restrict__ etype, int ntiles, int T)
{
    extern __shared__ char dynsmem[];
    uint32_t sb0 = smem_u32(dynsmem);
    uint32_t sb  = (sb0 + 1023) & ~1023u;
    char* smp = dynsmem + (sb - sb0);

    const int tid = threadIdx.x;
    int* s_meta = (int*)smp;
    int* s_src  = (int*)(smp + 16);
    int* s_dst  = (int*)(smp + 528);
    const uint32_t SB_B = sb + 2048;            // 4 chunks x 8KB resident B
    const uint32_t SB_A = SB_B + 32768;         // 4-buffer A ring

    // ---- loader geometry
    const int r0 = tid >> 2, qid = tid & 3;
    const uint32_t sd0 = (uint32_t)r0 * 64 + (uint32_t)((qid * 16) ^ ((r0 & 6) << 3));
    const uint32_t sd1 = sd0 + 64 * 64;

    // ---- fragment geometry
    const int L  = tid & 31, wid = tid >> 5;
    const int wm = (wid & 1) * 64, wn = (wid >> 1) * 32;
    const int lr15 = L & 15;
    const uint32_t swz = (uint32_t)((lr15 & 6) << 3);
    const uint32_t rowA = (uint32_t)(wm + lr15) * 64;
    const uint32_t rowB = (uint32_t)(wn + lr15) * 64;
    uint32_t cbx[2];
#pragma unroll
    for (int ks = 0; ks < 2; ks++)
        cbx[ks] = (uint32_t)(((L >> 4) * 16 + ks * 32)) ^ swz;

    const int tbeg = blockIdx.x * T;
    int tend = tbeg + T;
    if (tend > ntiles) tend = ntiles;
    int curRel = -1;

    for (int t = tbeg; t < tend; ++t) {
        __syncthreads();                       // prev epilogue done with s_dst
        if (tid < 128) {
            int e = g_perm[t * 128 + tid];
            s_src[tid] = (e >= 0) ? src[e] : 0;
            s_dst[tid] = (e >= 0) ? dst[e] : -1;
            if (tid == 0) s_meta[0] = (e >= 0) ? etype[e] : -1;
        }
        __syncthreads();
        const int rel = s_meta[0];
        if (rel < 0) continue;                 // fully-padded tile

        if (rel != curRel) {
            // load resident B: whole W_rel[rel] (32KB, 4 chunks), one group
            const __half* pbr = g_wrelT + (size_t)rel * 16384;
#pragma unroll
            for (int c = 0; c < 4; ++c) {
                const size_t b0 = (size_t)r0 * 128 + c * 32 + (size_t)qid * 8;
                CPA16(SB_B + c * 8192 + sd0, (const char*)(pbr + b0));
                CPA16(SB_B + c * 8192 + sd1, (const char*)(pbr + b0 + 64 * 128));
            }
            CPA_COMMIT();
            curRel = rel;
        }

        const int arow0 = s_src[r0], arow1 = s_src[r0 + 64];
        auto issueA = [&](int c) {
            const size_t a0 = (size_t)arow0 * 128 + (size_t)c * 32 + (size_t)qid * 8;
            const size_t a1 = (size_t)arow1 * 128 + (size_t)c * 32 + (size_t)qid * 8;
            const uint32_t A = SB_A + (uint32_t)(c & 3) * TILE_B;
            CPA16(A + sd0, (const char*)(g_xh + a0));
            CPA16(A + sd1, (const char*)(g_xh + a1));
            CPA_COMMIT();
        };
        issueA(0); issueA(1); issueA(2);

        float acc[4][4][4];
#pragma unroll
        for (int mi = 0; mi < 4; mi++)
#pragma unroll
            for (int ni = 0; ni < 4; ni++)
#pragma unroll
                for (int q = 0; q < 4; q++) acc[mi][ni][q] = 0.0f;

#pragma unroll 1
        for (int c = 0; c < 4; ++c) {
            const int rem = 3 - c;
            if (rem >= 2)      CPA_WAIT2();   // FIFO: (B,)A0..Ac complete
            else if (rem == 1) CPA_WAIT1();
            else               CPA_WAIT0();
            __syncthreads();
            if (c + 3 < 4) issueA(c + 3);

            const uint32_t A = SB_A + (uint32_t)(c & 3) * TILE_B;
            const uint32_t B = SB_B + (uint32_t)c * 8192;
#pragma unroll
            for (int ks = 0; ks < 2; ++ks) {
                const uint32_t ko = cbx[ks];
                uint32_t aF[4][4], bF[4][2];
                {
                    uint32_t bq[4], bq2[4];
                    ldsm4(bq,  B + rowB + ko);
                    ldsm4(bq2, B + rowB + 1024 + ko);
                    bF[0][0] = bq[0];  bF[0][1] = bq[2];
                    bF[1][0] = bq[1];  bF[1][1] = bq[3];
                    bF[2][0] = bq2[0]; bF[2][1] = bq2[2];
                    bF[3][0] = bq2[1]; bF[3][1] = bq2[3];
                }
#pragma unroll
                for (int mi = 0; mi < 4; ++mi)
                    ldsm4(aF[mi], A + rowA + mi * 1024 + ko);
#pragma unroll
                for (int mi = 0; mi < 4; ++mi)
#pragma unroll
                    for (int ni = 0; ni < 4; ++ni)
                        mma16816(acc[mi][ni], aF[mi], bF[ni]);
            }
        }

        // ---- epilogue: shfl-pack quads -> red.global.add.v4.f32 into S ----
        const int g = L >> 2;
        const int niA = (L & 1) * 2;
        const int half = (L & 3) >> 1;
#pragma unroll
        for (int mi = 0; mi < 4; ++mi)
#pragma unroll
            for (int h = 0; h < 2; ++h) {
                int lr = wm + mi * 16 + g + h * 8;
                int d = s_dst[lr];
                float q[4][4];
#pragma unroll
                for (int ni = 0; ni < 4; ++ni) {
                    float vx = acc[mi][ni][h * 2];
                    float vy = acc[mi][ni][h * 2 + 1];
                    float px = __shfl_xor_sync(0xFFFFFFFFu, vx, 1);
                    float py = __shfl_xor_sync(0xFFFFFFFFu, vy, 1);
                    if ((L & 1) == 0) { q[ni][0] = vx; q[ni][1] = vy; q[ni][2] = px; q[ni][3] = py; }
                    else              { q[ni][0] = px; q[ni][1] = py; q[ni][2] = vx; q[ni][3] = vy; }
                }
                if (d >= 0) {
                    float* bp = g_msg + (size_t)d * 128 + wn + half * 4;
                    asm volatile("red.global.add.v4.f32 [%0], {%1, %2, %3, %4};"
                        :: "l"(bp + niA * 8),
                           "f"(q[niA][0]), "f"(q[niA][1]),
                           "f"(q[niA][2]), "f"(q[niA][3]) : "memory");
                    asm volatile("red.global.add.v4.f32 [%0], {%1, %2, %3, %4};"
                        :: "l"(bp + (niA + 1) * 8),
                           "f"(q[niA + 1][0]), "f"(q[niA + 1][1]),
                           "f"(q[niA + 1][2]), "f"(q[niA + 1][3]) : "memory");
                }
            }
    }
}

// ---------------------------------------------------------------------------
// Dense fp16 HMMA GEMM. MODE: 2=MLP1, 3=MLP2 (as in R13)
// ---------------------------------------------------------------------------
static constexpr int STAGE_B = 2 * TILE_B;           // 16 KB
static constexpr int NSTAGE  = 4;
static constexpr int SMEM_DYN = 1024 + 2048 + NSTAGE * STAGE_B;

template<int MODE>
__global__ void __launch_bounds__(256, 2)
gemm_rgcn(const float* __restrict__ bias, float* __restrict__ outp, int N)
{
    constexpr int CH   = (MODE == 2) ? 8 : 12;
    constexpr int KTOT = (MODE == 2) ? 256 : 384;

    extern __shared__ char dynsmem[];
    uint32_t sb0 = smem_u32(dynsmem);
    uint32_t sb  = (sb0 + 1023) & ~1023u;

    const int tid = threadIdx.x;
    const int coloff = blockIdx.y * 128;
    const int rowbase = blockIdx.x * 128;
    const uint32_t STG0 = sb + 2048;

    const int r0 = tid >> 2, qid = tid & 3;
    int arow0 = rowbase + r0;      if (arow0 > N - 1) arow0 = N - 1;
    int arow1 = rowbase + r0 + 64; if (arow1 > N - 1) arow1 = N - 1;
    const uint32_t sd0 = (uint32_t)r0 * 64 + (uint32_t)((qid * 16) ^ ((r0 & 6) << 3));
    const uint32_t sd1 = sd0 + 64 * 64;

    const int L  = tid & 31, wid = tid >> 5;
    const int wm = (wid & 1) * 64, wn = (wid >> 1) * 32;
    const int lr15 = L & 15;
    const uint32_t swz = (uint32_t)((lr15 & 6) << 3);
    const uint32_t rowA = (uint32_t)(wm + lr15) * 64;
    const uint32_t rowB = (uint32_t)(wn + lr15) * 64;
    uint32_t cbx[2];
#pragma unroll
    for (int ks = 0; ks < 2; ks++)
        cbx[ks] = (uint32_t)(((L >> 4) * 16 + ks * 32)) ^ swz;

    float acc[4][4][4];
#pragma unroll
    for (int mi = 0; mi < 4; mi++)
#pragma unroll
        for (int ni = 0; ni < 4; ni++)
#pragma unroll
            for (int q = 0; q < 4; q++) acc[mi][ni][q] = 0.0f;

    auto issue = [&](int c) {
        const __half *pa, *pb;
        size_t ka, abase;
        if (MODE == 2 && c >= 4)      { pa = g_msgh; ka = 128; abase = (size_t)(c - 4) * 32; }
        else if (MODE == 3 && c >= 4) { pa = g_midh; ka = 256; abase = (size_t)(c - 4) * 32; }
        else                          { pa = g_xh;   ka = 128; abase = (size_t)c * 32; }
        pb = (MODE == 2) ? g_w1T : g_w2T;
        const size_t a0 = (size_t)arow0 * ka + abase + (size_t)qid * 8;
        const size_t a1 = (size_t)arow1 * ka + abase + (size_t)qid * 8;
        const size_t b0 = (size_t)(coloff + r0) * KTOT + (size_t)c * 32 + (size_t)qid * 8;
        const size_t b1 = b0 + (size_t)64 * KTOT;
        const uint32_t ST = STG0 + (uint32_t)(c % NSTAGE) * STAGE_B;
        const uint32_t A = ST, B = ST + TILE_B;
        CPA16(A + sd0, (const char*)(pa + a0));
        CPA16(A + sd1, (const char*)(pa + a1));
        CPA16(B + sd0, (const char*)(pb + b0));
        CPA16(B + sd1, (const char*)(pb + b1));
        CPA_COMMIT();
    };

    issue(0);
    issue(1);
    issue(2);

#pragma unroll 1
    for (int c = 0; c < CH; ++c) {
        const int rem = CH - 1 - c;
        if (rem >= 2)      CPA_WAIT2();
        else if (rem == 1) CPA_WAIT1();
        else               CPA_WAIT0();
        __syncthreads();
        if (c + 3 < CH) issue(c + 3);

        const uint32_t ST = STG0 + (uint32_t)(c % NSTAGE) * STAGE_B;
        const uint32_t A = ST, B = ST + TILE_B;

#pragma unroll
        for (int ks = 0; ks < 2; ++ks) {
            const uint32_t ko = cbx[ks];
            uint32_t aF[4][4], bF[4][2];
            {
                uint32_t bq[4], bq2[4];
                ldsm4(bq,  B + rowB + ko);
                ldsm4(bq2, B + rowB + 1024 + ko);
                bF[0][0] = bq[0];  bF[0][1] = bq[2];
                bF[1][0] = bq[1];  bF[1][1] = bq[3];
                bF[2][0] = bq2[0]; bF[2][1] = bq2[2];
                bF[3][0] = bq2[1]; bF[3][1] = bq2[3];
            }
#pragma unroll
            for (int mi = 0; mi < 4; ++mi)
                ldsm4(aF[mi], A + rowA + mi * 1024 + ko);
#pragma unroll
            for (int mi = 0; mi < 4; ++mi)
#pragma unroll
                for (int ni = 0; ni < 4; ++ni)
                    mma16816(acc[mi][ni], aF[mi], bF[ni]);
        }
    }

    const int g = L >> 2, t2 = (L & 3) * 2;
    if constexpr (MODE == 2) {
        float2 bb[4];
#pragma unroll
        for (int ni = 0; ni < 4; ++ni)
            bb[ni] = *(const float2*)(bias + coloff + wn + ni * 8 + t2);
#pragma unroll
        for (int mi = 0; mi < 4; ++mi)
#pragma unroll
            for (int h = 0; h < 2; ++h) {
                int r = rowbase + wm + mi * 16 + g + h * 8;
                if (r > N - 1) r = N - 1;
                size_t off = (size_t)r * 256 + coloff + wn + t2;
#pragma unroll
                for (int ni = 0; ni < 4; ++ni) {
                    float vx = tanh_fast(acc[mi][ni][h * 2]     + bb[ni].x);
                    float vy = tanh_fast(acc[mi][ni][h * 2 + 1] + bb[ni].y);
                    *(uint32_t*)((unsigned short*)g_midh + off + ni * 8) =
                        pack2h(vx, vy);
                }
            }
    } else {
        float2 bb[4];
#pragma unroll
        for (int ni = 0; ni < 4; ++ni)
            bb[ni] = *(const float2*)(bias + wn + ni * 8 + t2);
#pragma unroll
        for (int mi = 0; mi < 4; ++mi)
#pragma unroll
            for (int h = 0; h < 2; ++h) {
                int r = rowbase + wm + mi * 16 + g + h * 8;
                if (r > N - 1) r = N - 1;
                float* rp = outp + (size_t)r * 128 + wn + t2;
#pragma unroll
                for (int ni = 0; ni < 4; ++ni) {
                    float2 v;
                    v.x = acc[mi][ni][h * 2]     + bb[ni].x;
                    v.y = acc[mi][ni][h * 2 + 1] + bb[ni].y;
                    *(float2*)(rp + ni * 8) = v;
                }
            }
    }
}

// ---------------------------------------------------------------------------
extern "C" void kernel_launch(void* const* d_in, const int* in_sizes, int n_in,
                              void* d_out, int out_size)
{
    const float* x        = (const float*)d_in[0];
    const int*   src      = (const int*)  d_in[1];
    const int*   dst      = (const int*)  d_in[2];
    const int*   etype    = (const int*)  d_in[3];
    const float* W_rel    = (const float*)d_in[4];
    const float* loop_w   = (const float*)d_in[5];
    const float* rel_bias = (const float*)d_in[6];
    const float* W1       = (const float*)d_in[7];
    const float* b1       = (const float*)d_in[8];
    const float* W2       = (const float*)d_in[9];
    const float* b2       = (const float*)d_in[10];
    float* out = (float*)d_out;

    const int N = in_sizes[0] / 128;
    const int E = in_sizes[1];

    float *msg, *b1eff;
    __half *xh, *msgh;
    cudaGetSymbolAddress((void**)&msg,   g_msg);
    cudaGetSymbolAddress((void**)&b1eff, g_b1eff);
    cudaGetSymbolAddress((void**)&xh,    g_xh);
    cudaGetSymbolAddress((void**)&msgh,  g_msgh);

    cudaFuncSetAttribute(k_edge,       cudaFuncAttributeMaxDynamicSharedMemorySize, SMEM_E);
    cudaFuncSetAttribute(gemm_rgcn<2>, cudaFuncAttributeMaxDynamicSharedMemorySize, SMEM_DYN);
    cudaFuncSetAttribute(gemm_rgcn<3>, cudaFuncAttributeMaxDynamicSharedMemorySize, SMEM_DYN);

    const int P = E + PERM_PAD;
    const int tilesM = (N + 127) / 128;
    const int ntiles = P / 128;
    // persistent edge kernel: ~2 full waves (2 CTAs/SM x 148 SMs x 2)
    int T = (ntiles + 591) / 592;
    if (T < 1) T = 1;
    const int gridE = (ntiles + T - 1) / T;

    // 1. convert x to fp16 (also zeroes S, g_cnt, g_cur)
    k_cvtx<<<(N * 32 + 255) / 256, 256>>>(x, xh, N * 32);
    // 2. perm init + relation histogram + W_rel transpose (merged)
    k_prep<<<(P + 255) / 256, 256>>>(etype, E, P, W_rel);
    // 3. counting-sort scatter by relation
    k_scatter<<<(E + 255) / 256, 256>>>(etype, E);
    // 4. S += segsum_dst( x[src] @ W_rel[etype] )  (persistent, resident B)
    k_edge<<<gridE, 256, SMEM_E>>>(src, dst, etype, ntiles, T);
    // 5. fold loop_w / rel_bias into W1 -> w1T, b1eff
    k_foldw1<<<(256 * 256 + 256 + 255) / 256, 256>>>(W1, loop_w, rel_bias, b1);
    // 6. W2 transpose
    k_prepw2<<<(384 * 128 + 255) / 256, 256>>>(W2);
    // 7. convert S to fp16
    k_cvt<<<(N * 32 + 255) / 256, 256>>>(msg, msgh, N * 32);
    // 8. mid = tanh(x @ w1x' + S @ w1m + b1eff) -> fp16
    gemm_rgcn<2><<<dim3(tilesM, 2), 256, SMEM_DYN>>>(b1eff, nullptr, N);
    // 9. out = [x, mid] @ W2 + b2
    gemm_rgcn<3><<<tilesM, 256, SMEM_DYN>>>(b2, out, N);
}